// round 11
// baseline (speedup 1.0000x reference)
#include <cuda_runtime.h>
#include <math.h>

#define Nn 100000
#define Ee 1600000
#define Dd 32
#define Kk 1024
#define HALF_E (Ee/2)
#define HALF_N (Nn/2)

#define PARTITIONABLE 1

#define GB   148
#define GBT  1024
#define GT   (GB * GBT)
#define CH   ((Nn + GB - 1) / GB)

#define CAND 4096

// ---------------- scratch ----------------
__device__ int      g_counts[Nn];        // zeroed initially + by compact each run
__device__ int      g_rowptr[Nn + 1];
__device__ int      g_cursor[Nn];
__device__ int      g_eid[Ee];
__device__ __align__(16) float2 g_cv0[Ee];
__device__ __align__(16) float2 g_cv1[Ee];
__device__ __align__(16) float2 g_cv2[Ee];
__device__ __align__(16) float2 g_cv3[Ee];
__device__ float    g_order0[Nn], g_order1[Nn], g_order2[Nn];
__device__ float    g_embA[Nn * Dd], g_embB[Nn * Dd], g_embS[Nn * Dd];
__device__ float    g_numA[Nn], g_numB[Nn], g_numS[Nn];
__device__ float    g_gumbel[Nn];
__device__ unsigned g_keys[Nn];
__device__ unsigned g_hist16[65536];     // zeroed by build each run
__device__ unsigned g_vbin;
__device__ int      g_cntG;
__device__ unsigned long long g_cand[CAND];
__device__ int      g_bsum[GB];
__device__ int      g_boff[GB];
__device__ unsigned g_bar[8];            // zeroed initially + by compact each run

// ---------------- threefry-2x32 (JAX schedule) ----------------
__host__ __device__ __forceinline__ void tf2x32(unsigned k0, unsigned k1,
                                                unsigned x0, unsigned x1,
                                                unsigned& o0, unsigned& o1) {
    unsigned k2 = k0 ^ k1 ^ 0x1BD11BDAu;
    x0 += k0; x1 += k1;
#define TFR(r) { x0 += x1; x1 = (x1 << r) | (x1 >> (32 - r)); x1 ^= x0; }
    TFR(13) TFR(15) TFR(26) TFR(6)   x0 += k1; x1 += k2 + 1u;
    TFR(17) TFR(29) TFR(16) TFR(24)  x0 += k2; x1 += k0 + 2u;
    TFR(13) TFR(15) TFR(26) TFR(6)   x0 += k0; x1 += k1 + 3u;
    TFR(17) TFR(29) TFR(16) TFR(24)  x0 += k1; x1 += k2 + 4u;
    TFR(13) TFR(15) TFR(26) TFR(6)   x0 += k2; x1 += k0 + 5u;
#undef TFR
    o0 = x0; o1 = x1;
}

__device__ __forceinline__ float bits_to_uniform(unsigned bits) {
    return __fsub_rn(__uint_as_float((bits >> 9) | 0x3f800000u), 1.0f);
}

__device__ __forceinline__ unsigned edge_bits(unsigned k0, unsigned k1, int e) {
#if PARTITIONABLE
    unsigned o0, o1;
    tf2x32(k0, k1, 0u, (unsigned)e, o0, o1);
    return o0 ^ o1;
#else
    unsigned o0, o1;
    if (e < HALF_E) { tf2x32(k0, k1, (unsigned)e, (unsigned)(e + HALF_E), o0, o1); return o0; }
    else            { tf2x32(k0, k1, (unsigned)(e - HALF_E), (unsigned)e, o0, o1); return o1; }
#endif
}

__device__ __forceinline__ float2 packcv(int c, float v) {
    float2 r; r.x = __int_as_float(c); r.y = v; return r;
}

// ---------------- accurate fp32 natural log (double-float, ~1e-10 rel) ----------------
__device__ float log_acc(float x) {
    if (x == 0.0f) return -INFINITY;
    if (isinf(x)) return INFINITY;
    int ix = __float_as_int(x);
    int e = ((ix >> 23) & 0xFF) - 127;
    float m = __int_as_float((ix & 0x007FFFFF) | 0x3F800000);
    if (m > 1.41421356f) { m *= 0.5f; e += 1; }
    float a = m - 1.0f;
    float bh = m + 1.0f;
    float bl;
    {
        float bp = bh - 1.0f;
        float ap = bh - bp;
        bl = (1.0f - ap) + (m - bp);
    }
    float q0 = a / bh;
    float r  = fmaf(-q0, bh, a);
    r = fmaf(-q0, bl, r);
    float q1 = r / bh;
    float th = q0 * q0;
    float tl = fmaf(q0, q0, -th);
    tl = fmaf(2.0f * q0, q1, tl);
    const float C3H = 0.333333343f;
    const float C3L = -9.93410830e-09f;
    float t2 = th * th;
    float tail = t2 * (0.2f + th * (0.14285714f + th * (0.11111111f +
                 th * (0.090909091f + th * 0.076923077f))));
    float Rh = th * C3H;
    float Rl = fmaf(th, C3H, -Rh);
    Rl += tl * C3H + th * C3L + tail;
    float twq0 = 2.0f * q0;
    float ph = twq0 * Rh;
    float pl = fmaf(twq0, Rh, -ph);
    pl += twq0 * Rl + 2.0f * q1 * Rh;
    float lh = twq0 + ph;
    float z = lh - twq0;
    float ll = (twq0 - (lh - z)) + (ph - z);
    ll += 2.0f * q1 + pl;
    const float LN2H = 0.693145751953125f;
    const float LN2L = 1.4286067653e-06f;
    float fe = (float)e;
    float eh = fe * LN2H;
    float el = fe * LN2L;
    float sh = eh + lh;
    float zz = sh - eh;
    float sl = (eh - (sh - zz)) + (lh - zz);
    return sh + (sl + el + ll);
}

// grid-wide barrier: all GB blocks co-resident (grid == #SMs, occ 1).
__device__ __forceinline__ void gridbar(int id) {
    __syncthreads();
    if (threadIdx.x == 0) {
        __threadfence();
        atomicAdd(&g_bar[id], 1u);
        while (*((volatile unsigned*)&g_bar[id]) < (unsigned)GB) { }
        __threadfence();
    }
    __syncthreads();
}

// ---------------- fused CSR build ----------------
__global__ void __launch_bounds__(GBT, 1) build_kernel(
        const int* __restrict__ rows, const int* __restrict__ cols,
        const float* __restrict__ adj,
        unsigned a0, unsigned a1, unsigned b0, unsigned b1,
        unsigned c0, unsigned c1) {
    int b = blockIdx.x, tid = threadIdx.x;
    int gt = b * GBT + tid;

    // Phase A: zero hist16 + count
    for (int i = gt; i < 65536; i += GT) g_hist16[i] = 0u;
    for (int e = gt; e < Ee; e += GT) atomicAdd(&g_counts[rows[e]], 1);
    gridbar(0);

    // Phase B: scan
    __shared__ int sh[GBT];
    int idx = b * CH + tid;
    int v = (tid < CH && idx < Nn) ? g_counts[idx] : 0;
    sh[tid] = v;
    __syncthreads();
#pragma unroll
    for (int off = 1; off < GBT; off <<= 1) {
        int t = (tid >= off) ? sh[tid - off] : 0;
        __syncthreads();
        sh[tid] += t;
        __syncthreads();
    }
    if (tid == GBT - 1) g_bsum[b] = sh[GBT - 1];
    int myincl = sh[tid];
    gridbar(1);
    if (b == 0 && tid == 0) {
        int acc = 0;
        for (int i = 0; i < GB; i++) { g_boff[i] = acc; acc += g_bsum[i]; }
        g_rowptr[Nn] = acc;
    }
    gridbar(2);
    if (tid < CH && idx < Nn) {
        int val = g_boff[b] + myincl - v;
        g_rowptr[idx] = val;
        g_cursor[idx] = val;
    }
    gridbar(3);

    // Phase C: scatter
    for (int e = gt; e < Ee; e += GT) {
        int pos = atomicAdd(&g_cursor[rows[e]], 1);
        g_eid[pos] = e;
    }
    gridbar(4);

    // Phase D: sortfill — warp per row
    int lane = tid & 31;
    int wstride = GT >> 5;
    for (int w = (gt >> 5); w < Nn; w += wstride) {
        int s = g_rowptr[w], t = g_rowptr[w + 1];
        int deg = t - s;
        if (deg <= 32) {
            int eid = (lane < deg) ? g_eid[s + lane] : 0x7FFFFFFF;
#pragma unroll
            for (int k = 2; k <= 32; k <<= 1) {
#pragma unroll
                for (int j = k >> 1; j > 0; j >>= 1) {
                    int other = __shfl_xor_sync(0xffffffffu, eid, j);
                    bool up = ((lane & k) == 0);
                    bool lower = ((lane & j) == 0);
                    int mn = min(eid, other), mx = max(eid, other);
                    eid = (lower == up) ? mn : mx;
                }
            }
            int   c  = 0;
            float v0 = 0.f, v1 = 0.f, v2 = 0.f, v3 = 0.f;
            if (lane < deg) {
                c  = cols[eid];
                v0 = adj[eid];
                float k0f = floorf(__fadd_rn(bits_to_uniform(edge_bits(a0, a1, eid)), 0.5f));
                v1 = __fmul_rn(v0, k0f);
                float k1f = floorf(__fadd_rn(bits_to_uniform(edge_bits(b0, b1, eid)), 0.25f));
                v2 = __fmul_rn(v1, k1f);
                float k2f = floorf(__fadd_rn(bits_to_uniform(edge_bits(c0, c1, eid)), 0.125f));
                v3 = __fmul_rn(v2, k2f);
                g_cv0[s + lane] = packcv(c, v0);
                g_cv1[s + lane] = packcv(c, v1);
                g_cv2[s + lane] = packcv(c, v2);
                g_cv3[s + lane] = packcv(c, v3);
            }
            float o0a = 0.f, o1a = 0.f, o2a = 0.f;
#pragma unroll
            for (int d = 0; d < 32; d++) {
                o0a = __fadd_rn(o0a, __shfl_sync(0xffffffffu, v0, d));
                o1a = __fadd_rn(o1a, __shfl_sync(0xffffffffu, v1, d));
                o2a = __fadd_rn(o2a, __shfl_sync(0xffffffffu, v2, d));
            }
            if (lane == 0) { g_order0[w] = o0a; g_order1[w] = o1a; g_order2[w] = o2a; }
        } else if (lane == 0) {
            for (int a = s + 1; a < t; a++) {
                int x = g_eid[a]; int bb = a - 1;
                while (bb >= s && g_eid[bb] > x) { g_eid[bb + 1] = g_eid[bb]; bb--; }
                g_eid[bb + 1] = x;
            }
            float o0a = 0.f, o1a = 0.f, o2a = 0.f;
            for (int q = s; q < t; q++) {
                int eid = g_eid[q];
                int c = cols[eid];
                float v0 = adj[eid];
                float k0f = floorf(__fadd_rn(bits_to_uniform(edge_bits(a0, a1, eid)), 0.5f));
                float v1 = __fmul_rn(v0, k0f);
                float k1f = floorf(__fadd_rn(bits_to_uniform(edge_bits(b0, b1, eid)), 0.25f));
                float v2 = __fmul_rn(v1, k1f);
                float k2f = floorf(__fadd_rn(bits_to_uniform(edge_bits(c0, c1, eid)), 0.125f));
                float v3 = __fmul_rn(v2, k2f);
                g_cv0[q] = packcv(c, v0);
                g_cv1[q] = packcv(c, v1);
                g_cv2[q] = packcv(c, v2);
                g_cv3[q] = packcv(c, v3);
                o0a = __fadd_rn(o0a, v0);
                o1a = __fadd_rn(o1a, v1);
                o2a = __fadd_rn(o2a, v2);
            }
            g_order0[w] = o0a; g_order1[w] = o1a; g_order2[w] = o2a;
        }
    }
}

// ---------------- gumbel noise ----------------
__global__ void gumbel_kernel() {
    int n = blockIdx.x * blockDim.x + threadIdx.x;
    if (n >= Nn) return;
    unsigned bits;
#if PARTITIONABLE
    unsigned o0, o1;
    tf2x32(0u, 7u, 0u, (unsigned)n, o0, o1);
    bits = o0 ^ o1;
#else
    unsigned o0, o1;
    if (n < HALF_N) { tf2x32(0u, 7u, (unsigned)n, (unsigned)(n + HALF_N), o0, o1); bits = o0; }
    else            { tf2x32(0u, 7u, (unsigned)(n - HALF_N), (unsigned)n, o0, o1); bits = o1; }
#endif
    float u = bits_to_uniform(bits);
    float lu = log_acc(u);
    float g  = -log_acc(-lu);
    g_gumbel[n] = g;
}

// ---------------- propagation ----------------
__global__ void emb0_kernel(const float* __restrict__ X) {
    int w = (blockIdx.x * blockDim.x + threadIdx.x) >> 5;
    int lane = threadIdx.x & 31;
    if (w >= Nn) return;
    int s = g_rowptr[w], t = g_rowptr[w + 1];
    float acc = 0.f;
    int p = s;
    if ((p & 1) && p < t) {
        float2 a = g_cv0[p];
        acc = __fadd_rn(acc, __fmul_rn(a.y, X[__float_as_int(a.x) * Dd + lane]));
        p++;
    }
    for (; p + 8 <= t; p += 8) {
        float4 q0 = *(const float4*)&g_cv0[p];
        float4 q1 = *(const float4*)&g_cv0[p + 2];
        float4 q2 = *(const float4*)&g_cv0[p + 4];
        float4 q3 = *(const float4*)&g_cv0[p + 6];
        float x0 = X[__float_as_int(q0.x) * Dd + lane];
        float x1 = X[__float_as_int(q0.z) * Dd + lane];
        float x2 = X[__float_as_int(q1.x) * Dd + lane];
        float x3 = X[__float_as_int(q1.z) * Dd + lane];
        float x4 = X[__float_as_int(q2.x) * Dd + lane];
        float x5 = X[__float_as_int(q2.z) * Dd + lane];
        float x6 = X[__float_as_int(q3.x) * Dd + lane];
        float x7 = X[__float_as_int(q3.z) * Dd + lane];
        acc = __fadd_rn(acc, __fmul_rn(q0.y, x0));
        acc = __fadd_rn(acc, __fmul_rn(q0.w, x1));
        acc = __fadd_rn(acc, __fmul_rn(q1.y, x2));
        acc = __fadd_rn(acc, __fmul_rn(q1.w, x3));
        acc = __fadd_rn(acc, __fmul_rn(q2.y, x4));
        acc = __fadd_rn(acc, __fmul_rn(q2.w, x5));
        acc = __fadd_rn(acc, __fmul_rn(q3.y, x6));
        acc = __fadd_rn(acc, __fmul_rn(q3.w, x7));
    }
    for (; p < t; p++) {
        float2 a = g_cv0[p];
        acc = __fadd_rn(acc, __fmul_rn(a.y, X[__float_as_int(a.x) * Dd + lane]));
    }
    float e0 = __fsub_rn(acc, X[w * Dd + lane]);
    g_embA[w * Dd + lane] = e0;
    g_embS[w * Dd + lane] = e0;
    if (lane == 0) {
        float o = g_order0[w];
        g_numA[w] = o;
        g_numS[w] = o;
    }
}

// num-chain fused: one edge per lane + strict lane-order predicated shuffle sum.
template <int SEL, int COMP, int FINAL>
__global__ void iter_kernel(const float* __restrict__ X, float* score_out) {
    const float2* __restrict__ cv = (COMP == 1) ? g_cv1 : ((COMP == 2) ? g_cv2 : g_cv3);
    const float* __restrict__ ord = (COMP == 1) ? g_order0 : ((COMP == 2) ? g_order1 : g_order2);
    const float* __restrict__ cur  = SEL ? g_embB : g_embA;
    float*       __restrict__ nxt  = SEL ? g_embA : g_embB;
    const float* __restrict__ curn = SEL ? g_numB : g_numA;
    float*       __restrict__ nxtn = SEL ? g_numA : g_numB;
    int w = (blockIdx.x * blockDim.x + threadIdx.x) >> 5;
    int lane = threadIdx.x & 31;
    if (w >= Nn) return;
    int s = g_rowptr[w], t = g_rowptr[w + 1];
    int deg = t - s;
    float accE = 0.f;
    int p = s;
    if ((p & 1) && p < t) {
        float2 a = cv[p];
        accE = __fadd_rn(accE, __fmul_rn(a.y, cur[__float_as_int(a.x) * Dd + lane]));
        p++;
    }
    for (; p + 8 <= t; p += 8) {
        float4 q0 = *(const float4*)&cv[p];
        float4 q1 = *(const float4*)&cv[p + 2];
        float4 q2 = *(const float4*)&cv[p + 4];
        float4 q3 = *(const float4*)&cv[p + 6];
        float x0 = cur[__float_as_int(q0.x) * Dd + lane];
        float x1 = cur[__float_as_int(q0.z) * Dd + lane];
        float x2 = cur[__float_as_int(q1.x) * Dd + lane];
        float x3 = cur[__float_as_int(q1.z) * Dd + lane];
        float x4 = cur[__float_as_int(q2.x) * Dd + lane];
        float x5 = cur[__float_as_int(q2.z) * Dd + lane];
        float x6 = cur[__float_as_int(q3.x) * Dd + lane];
        float x7 = cur[__float_as_int(q3.z) * Dd + lane];
        accE = __fadd_rn(accE, __fmul_rn(q0.y, x0));
        accE = __fadd_rn(accE, __fmul_rn(q0.w, x1));
        accE = __fadd_rn(accE, __fmul_rn(q1.y, x2));
        accE = __fadd_rn(accE, __fmul_rn(q1.w, x3));
        accE = __fadd_rn(accE, __fmul_rn(q2.y, x4));
        accE = __fadd_rn(accE, __fmul_rn(q2.w, x5));
        accE = __fadd_rn(accE, __fmul_rn(q3.y, x6));
        accE = __fadd_rn(accE, __fmul_rn(q3.w, x7));
    }
    for (; p < t; p++) {
        float2 a = cv[p];
        accE = __fadd_rn(accE, __fmul_rn(a.y, cur[__float_as_int(a.x) * Dd + lane]));
    }

    // ---- fused scalar num chain ----
    float accN = 0.f;
    if (deg <= 32) {
        float pn = 0.f;
        if (lane < deg) {
            float2 a = cv[s + lane];
            pn = __fmul_rn(a.y, curn[__float_as_int(a.x)]);
        }
#pragma unroll
        for (int d = 0; d < 32; d++) {
            float tv = __shfl_sync(0xffffffffu, pn, d);
            if (d < deg) accN = __fadd_rn(accN, tv);   // uniform predicate
        }
    } else {
        if (lane == 0) {
            for (int q = s; q < t; q++) {
                float2 a = cv[q];
                accN = __fadd_rn(accN, __fmul_rn(a.y, curn[__float_as_int(a.x)]));
            }
        }
        accN = __shfl_sync(0xffffffffu, accN, 0);
    }

    float o = ord[w];
    float ce = cur[w * Dd + lane];
    float outE = __fsub_rn(__fsub_rn(accE, ce), __fmul_rn(o, ce));
    float cn = curn[w];
    float outN = __fsub_rn(__fsub_rn(accN, cn), o);

    if (FINAL == 0) {
        nxt[w * Dd + lane] = outE;
        g_embS[w * Dd + lane] = __fadd_rn(g_embS[w * Dd + lane], outE);
        if (lane == 0) {
            nxtn[w] = outN;
            g_numS[w] = __fadd_rn(g_numS[w], outN);
        }
    } else {
        float embS = __fadd_rn(g_embS[w * Dd + lane], outE);
        float numS = __fadd_rn(g_numS[w], outN);
        float den = __fadd_rn(numS, 1e-8f);
        float sv = __fdiv_rn(embS, den);
        float ev = X[w * Dd + lane];

        float p1 = __fmul_rn(sv, sv);
        float sq = 0.f;
#pragma unroll
        for (int d = 0; d < 32; d++) sq = __fadd_rn(sq, __shfl_sync(0xffffffffu, p1, d));
        float nr = fmaxf(__fsqrt_rn(sq), 1e-12f);

        float p2 = __fmul_rn(ev, ev);
        float sq2 = 0.f;
#pragma unroll
        for (int d = 0; d < 32; d++) sq2 = __fadd_rn(sq2, __shfl_sync(0xffffffffu, p2, d));
        float nr2 = fmaxf(__fsqrt_rn(sq2), 1e-12f);

        float prod = __fmul_rn(__fdiv_rn(sv, nr), __fdiv_rn(ev, nr2));
        float dot = 0.f;
#pragma unroll
        for (int d = 0; d < 32; d++) dot = __fadd_rn(dot, __shfl_sync(0xffffffffu, prod, d));

        if (lane == 0) {
            float score = __fadd_rn(dot, g_gumbel[w]);
            if (score_out) score_out[w] = score;
            unsigned ub = __float_as_uint(score);
            unsigned key = (ub & 0x80000000u) ? ~ub : (ub | 0x80000000u);
            g_keys[w] = key;
            atomicAdd(&g_hist16[key >> 16], 1u);
        }
    }
}

// ---------------- top-k: 16-bit threshold -> compact -> exact sort ----------------
__global__ void select2_kernel() {
    __shared__ int coarse[1024];
    int tid = threadIdx.x;
    int sum = 0;
#pragma unroll 8
    for (int j = 0; j < 64; j++) sum += (int)g_hist16[tid * 64 + j];
    coarse[tid] = sum;
    __syncthreads();
    for (int off = 1; off < 1024; off <<= 1) {
        int v = (tid + off < 1024) ? coarse[tid + off] : 0;
        __syncthreads();
        coarse[tid] += v;
        __syncthreads();
    }
    int mySuf = coarse[tid];
    int nextSuf = (tid + 1 < 1024) ? coarse[tid + 1] : 0;
    if (mySuf >= Kk && nextSuf < Kk) {
        int cum = nextSuf;
        unsigned vbin = (unsigned)(tid * 64);
        for (int b = 63; b >= 0; b--) {
            cum += (int)g_hist16[tid * 64 + b];
            if (cum >= Kk) { vbin = (unsigned)(tid * 64 + b); break; }
        }
        g_vbin = vbin;
        g_cntG = 0;
    }
}

__global__ void compact_kernel() {
    int i = blockIdx.x * blockDim.x + threadIdx.x;
    if (i >= Nn) return;
    unsigned key = g_keys[i];
    if ((key >> 16) >= g_vbin) {
        int p = atomicAdd(&g_cntG, 1);
        if (p < CAND) g_cand[p] = (((unsigned long long)(~key)) << 32) | (unsigned)i;
    }
    g_counts[i] = 0;
    if (i < 8) g_bar[i] = 0u;
}

__global__ void topsort_kernel(float* cand_out) {
    __shared__ unsigned long long sg[CAND];
    int tid = threadIdx.x;
    int cnt = g_cntG; if (cnt > CAND) cnt = CAND;
    for (int t = tid; t < CAND; t += 1024)
        sg[t] = (t < cnt) ? g_cand[t] : 0xFFFFFFFFFFFFFFFFull;
    __syncthreads();
    for (int k = 2; k <= CAND; k <<= 1)
        for (int j = k >> 1; j > 0; j >>= 1) {
            for (int t = tid; t < CAND; t += 1024) {
                int ixj = t ^ j;
                if (ixj > t) {
                    bool up = ((t & k) == 0);
                    unsigned long long a = sg[t], b = sg[ixj];
                    if ((a > b) == up) { sg[t] = b; sg[ixj] = a; }
                }
            }
            __syncthreads();
        }
    if (tid < Kk && cand_out)
        cand_out[tid] = (float)(int)(sg[tid] & 0xFFFFFFFFull);
}

// ---------------- launch ----------------
extern "C" void kernel_launch(void* const* d_in, const int* in_sizes, int n_in,
                              void* d_out, int out_size) {
    const int*   edge_index = (const int*)d_in[0];
    const float* adj_values = (const float*)d_in[1];
    const float* embeds     = (const float*)d_in[2];
    const int* rows = edge_index;
    const int* cols = edge_index + Ee;
    float* out = (float*)d_out;

    float* score_out = nullptr;
    float* cand_out  = nullptr;
    if (out_size >= Nn + Kk)      { score_out = out; cand_out = out + Nn; }
    else if (out_size == Nn)      { score_out = out; }
    else if (out_size == Kk)      { cand_out = out; }
    else                          { score_out = out; }

    unsigned fk[3][2];
    for (int i = 0; i < 3; i++) tf2x32(0u, 42u, 0u, (unsigned)i, fk[i][0], fk[i][1]);

    const int TB = 256;
    int warpBlocks = (Nn * 32 + TB - 1) / TB;
    build_kernel<<<GB, GBT>>>(rows, cols, adj_values,               // 1
                              fk[0][0], fk[0][1],
                              fk[1][0], fk[1][1],
                              fk[2][0], fk[2][1]);
    gumbel_kernel<<<(Nn + TB - 1) / TB, TB>>>();                    // 2
    emb0_kernel<<<warpBlocks, TB>>>(embeds);                        // 3
    iter_kernel<0, 1, 0><<<warpBlocks, TB>>>(nullptr, nullptr);     // 4 <- ncu window
    iter_kernel<1, 2, 0><<<warpBlocks, TB>>>(nullptr, nullptr);     // 5
    iter_kernel<0, 3, 1><<<warpBlocks, TB>>>(embeds, score_out);    // 6 (score + hist)
    select2_kernel<<<1, 1024>>>();                                  // 7
    compact_kernel<<<(Nn + TB - 1) / TB, TB>>>();                   // 8 (+cleanup)
    topsort_kernel<<<1, 1024>>>(cand_out);                          // 9
}

// round 12
// speedup vs baseline: 1.1380x; 1.1380x over previous
#include <cuda_runtime.h>
#include <math.h>

#define Nn 100000
#define Ee 1600000
#define Dd 32
#define Kk 1024
#define HALF_E (Ee/2)
#define HALF_N (Nn/2)

#define PARTITIONABLE 1

#define GB   148
#define GBT  1024
#define GT   (GB * GBT)
#define CH   ((Nn + GB - 1) / GB)

// ---------------- scratch ----------------
__device__ int      g_counts[Nn];        // zeroed initially + by compact each run
__device__ int      g_rowptr[Nn + 1];
__device__ int      g_cursor[Nn];
__device__ int      g_eid[Ee];
__device__ __align__(16) float2 g_cv0[Ee];
__device__ __align__(16) float2 g_cv1[Ee];
__device__ __align__(16) float2 g_cv2[Ee];
__device__ __align__(16) float2 g_cv3[Ee];
__device__ float    g_order0[Nn], g_order1[Nn], g_order2[Nn];
__device__ float    g_embA[Nn * Dd], g_embB[Nn * Dd], g_embS[Nn * Dd];
__device__ float    g_numA[Nn], g_numB[Nn], g_numS[Nn];
__device__ float    g_gumbel[Nn];
__device__ unsigned g_keys[Nn];
__device__ unsigned g_kth;
__device__ int      g_cntG, g_cntE;
__device__ unsigned long long g_candG[2048];
__device__ int      g_candE[2048];
__device__ int      g_bsum[GB];
__device__ int      g_boff[GB];
__device__ unsigned g_bar[8];            // zeroed initially + by compact each run

// ---------------- threefry-2x32 (JAX schedule) ----------------
__host__ __device__ __forceinline__ void tf2x32(unsigned k0, unsigned k1,
                                                unsigned x0, unsigned x1,
                                                unsigned& o0, unsigned& o1) {
    unsigned k2 = k0 ^ k1 ^ 0x1BD11BDAu;
    x0 += k0; x1 += k1;
#define TFR(r) { x0 += x1; x1 = (x1 << r) | (x1 >> (32 - r)); x1 ^= x0; }
    TFR(13) TFR(15) TFR(26) TFR(6)   x0 += k1; x1 += k2 + 1u;
    TFR(17) TFR(29) TFR(16) TFR(24)  x0 += k2; x1 += k0 + 2u;
    TFR(13) TFR(15) TFR(26) TFR(6)   x0 += k0; x1 += k1 + 3u;
    TFR(17) TFR(29) TFR(16) TFR(24)  x0 += k1; x1 += k2 + 4u;
    TFR(13) TFR(15) TFR(26) TFR(6)   x0 += k2; x1 += k0 + 5u;
#undef TFR
    o0 = x0; o1 = x1;
}

__device__ __forceinline__ float bits_to_uniform(unsigned bits) {
    return __fsub_rn(__uint_as_float((bits >> 9) | 0x3f800000u), 1.0f);
}

__device__ __forceinline__ unsigned edge_bits(unsigned k0, unsigned k1, int e) {
#if PARTITIONABLE
    unsigned o0, o1;
    tf2x32(k0, k1, 0u, (unsigned)e, o0, o1);
    return o0 ^ o1;
#else
    unsigned o0, o1;
    if (e < HALF_E) { tf2x32(k0, k1, (unsigned)e, (unsigned)(e + HALF_E), o0, o1); return o0; }
    else            { tf2x32(k0, k1, (unsigned)(e - HALF_E), (unsigned)e, o0, o1); return o1; }
#endif
}

__device__ __forceinline__ float2 packcv(int c, float v) {
    float2 r; r.x = __int_as_float(c); r.y = v; return r;
}

// ---------------- accurate fp32 natural log (double-float, ~1e-10 rel) ----------------
__device__ float log_acc(float x) {
    if (x == 0.0f) return -INFINITY;
    if (isinf(x)) return INFINITY;
    int ix = __float_as_int(x);
    int e = ((ix >> 23) & 0xFF) - 127;
    float m = __int_as_float((ix & 0x007FFFFF) | 0x3F800000);
    if (m > 1.41421356f) { m *= 0.5f; e += 1; }
    float a = m - 1.0f;
    float bh = m + 1.0f;
    float bl;
    {
        float bp = bh - 1.0f;
        float ap = bh - bp;
        bl = (1.0f - ap) + (m - bp);
    }
    float q0 = a / bh;
    float r  = fmaf(-q0, bh, a);
    r = fmaf(-q0, bl, r);
    float q1 = r / bh;
    float th = q0 * q0;
    float tl = fmaf(q0, q0, -th);
    tl = fmaf(2.0f * q0, q1, tl);
    const float C3H = 0.333333343f;
    const float C3L = -9.93410830e-09f;
    float t2 = th * th;
    float tail = t2 * (0.2f + th * (0.14285714f + th * (0.11111111f +
                 th * (0.090909091f + th * 0.076923077f))));
    float Rh = th * C3H;
    float Rl = fmaf(th, C3H, -Rh);
    Rl += tl * C3H + th * C3L + tail;
    float twq0 = 2.0f * q0;
    float ph = twq0 * Rh;
    float pl = fmaf(twq0, Rh, -ph);
    pl += twq0 * Rl + 2.0f * q1 * Rh;
    float lh = twq0 + ph;
    float z = lh - twq0;
    float ll = (twq0 - (lh - z)) + (ph - z);
    ll += 2.0f * q1 + pl;
    const float LN2H = 0.693145751953125f;
    const float LN2L = 1.4286067653e-06f;
    float fe = (float)e;
    float eh = fe * LN2H;
    float el = fe * LN2L;
    float sh = eh + lh;
    float zz = sh - eh;
    float sl = (eh - (sh - zz)) + (lh - zz);
    return sh + (sl + el + ll);
}

// grid-wide barrier: all GB blocks co-resident (grid == #SMs, occ 1).
__device__ __forceinline__ void gridbar(int id) {
    __syncthreads();
    if (threadIdx.x == 0) {
        __threadfence();
        atomicAdd(&g_bar[id], 1u);
        while (*((volatile unsigned*)&g_bar[id]) < (unsigned)GB) { }
        __threadfence();
    }
    __syncthreads();
}

// ---------------- fused CSR build ----------------
__global__ void __launch_bounds__(GBT, 1) build_kernel(
        const int* __restrict__ rows, const int* __restrict__ cols,
        const float* __restrict__ adj,
        unsigned a0, unsigned a1, unsigned b0, unsigned b1,
        unsigned c0, unsigned c1) {
    int b = blockIdx.x, tid = threadIdx.x;
    int gt = b * GBT + tid;

    // Phase A: count
    for (int e = gt; e < Ee; e += GT) atomicAdd(&g_counts[rows[e]], 1);
    gridbar(0);

    // Phase B: scan
    __shared__ int sh[GBT];
    int idx = b * CH + tid;
    int v = (tid < CH && idx < Nn) ? g_counts[idx] : 0;
    sh[tid] = v;
    __syncthreads();
#pragma unroll
    for (int off = 1; off < GBT; off <<= 1) {
        int t = (tid >= off) ? sh[tid - off] : 0;
        __syncthreads();
        sh[tid] += t;
        __syncthreads();
    }
    if (tid == GBT - 1) g_bsum[b] = sh[GBT - 1];
    int myincl = sh[tid];
    gridbar(1);
    if (b == 0 && tid == 0) {
        int acc = 0;
        for (int i = 0; i < GB; i++) { g_boff[i] = acc; acc += g_bsum[i]; }
        g_rowptr[Nn] = acc;
    }
    gridbar(2);
    if (tid < CH && idx < Nn) {
        int val = g_boff[b] + myincl - v;
        g_rowptr[idx] = val;
        g_cursor[idx] = val;
    }
    gridbar(3);

    // Phase C: scatter
    for (int e = gt; e < Ee; e += GT) {
        int pos = atomicAdd(&g_cursor[rows[e]], 1);
        g_eid[pos] = e;
    }
    gridbar(4);

    // Phase D: sortfill — warp per row
    int lane = tid & 31;
    int wstride = GT >> 5;
    for (int w = (gt >> 5); w < Nn; w += wstride) {
        int s = g_rowptr[w], t = g_rowptr[w + 1];
        int deg = t - s;
        if (deg <= 32) {
            int eid = (lane < deg) ? g_eid[s + lane] : 0x7FFFFFFF;
#pragma unroll
            for (int k = 2; k <= 32; k <<= 1) {
#pragma unroll
                for (int j = k >> 1; j > 0; j >>= 1) {
                    int other = __shfl_xor_sync(0xffffffffu, eid, j);
                    bool up = ((lane & k) == 0);
                    bool lower = ((lane & j) == 0);
                    int mn = min(eid, other), mx = max(eid, other);
                    eid = (lower == up) ? mn : mx;
                }
            }
            int   c  = 0;
            float v0 = 0.f, v1 = 0.f, v2 = 0.f, v3 = 0.f;
            if (lane < deg) {
                c  = cols[eid];
                v0 = adj[eid];
                float k0f = floorf(__fadd_rn(bits_to_uniform(edge_bits(a0, a1, eid)), 0.5f));
                v1 = __fmul_rn(v0, k0f);
                float k1f = floorf(__fadd_rn(bits_to_uniform(edge_bits(b0, b1, eid)), 0.25f));
                v2 = __fmul_rn(v1, k1f);
                float k2f = floorf(__fadd_rn(bits_to_uniform(edge_bits(c0, c1, eid)), 0.125f));
                v3 = __fmul_rn(v2, k2f);
                g_cv0[s + lane] = packcv(c, v0);
                g_cv1[s + lane] = packcv(c, v1);
                g_cv2[s + lane] = packcv(c, v2);
                g_cv3[s + lane] = packcv(c, v3);
            }
            float o0a = 0.f, o1a = 0.f, o2a = 0.f;
#pragma unroll
            for (int d = 0; d < 32; d++) {
                o0a = __fadd_rn(o0a, __shfl_sync(0xffffffffu, v0, d));
                o1a = __fadd_rn(o1a, __shfl_sync(0xffffffffu, v1, d));
                o2a = __fadd_rn(o2a, __shfl_sync(0xffffffffu, v2, d));
            }
            if (lane == 0) { g_order0[w] = o0a; g_order1[w] = o1a; g_order2[w] = o2a; }
        } else if (lane == 0) {
            for (int a = s + 1; a < t; a++) {
                int x = g_eid[a]; int bb = a - 1;
                while (bb >= s && g_eid[bb] > x) { g_eid[bb + 1] = g_eid[bb]; bb--; }
                g_eid[bb + 1] = x;
            }
            float o0a = 0.f, o1a = 0.f, o2a = 0.f;
            for (int q = s; q < t; q++) {
                int eid = g_eid[q];
                int c = cols[eid];
                float v0 = adj[eid];
                float k0f = floorf(__fadd_rn(bits_to_uniform(edge_bits(a0, a1, eid)), 0.5f));
                float v1 = __fmul_rn(v0, k0f);
                float k1f = floorf(__fadd_rn(bits_to_uniform(edge_bits(b0, b1, eid)), 0.25f));
                float v2 = __fmul_rn(v1, k1f);
                float k2f = floorf(__fadd_rn(bits_to_uniform(edge_bits(c0, c1, eid)), 0.125f));
                float v3 = __fmul_rn(v2, k2f);
                g_cv0[q] = packcv(c, v0);
                g_cv1[q] = packcv(c, v1);
                g_cv2[q] = packcv(c, v2);
                g_cv3[q] = packcv(c, v3);
                o0a = __fadd_rn(o0a, v0);
                o1a = __fadd_rn(o1a, v1);
                o2a = __fadd_rn(o2a, v2);
            }
            g_order0[w] = o0a; g_order1[w] = o1a; g_order2[w] = o2a;
        }
    }
}

// ---------------- gumbel noise ----------------
__global__ void gumbel_kernel() {
    int n = blockIdx.x * blockDim.x + threadIdx.x;
    if (n >= Nn) return;
    unsigned bits;
#if PARTITIONABLE
    unsigned o0, o1;
    tf2x32(0u, 7u, 0u, (unsigned)n, o0, o1);
    bits = o0 ^ o1;
#else
    unsigned o0, o1;
    if (n < HALF_N) { tf2x32(0u, 7u, (unsigned)n, (unsigned)(n + HALF_N), o0, o1); bits = o0; }
    else            { tf2x32(0u, 7u, (unsigned)(n - HALF_N), (unsigned)n, o0, o1); bits = o1; }
#endif
    float u = bits_to_uniform(bits);
    float lu = log_acc(u);
    float g  = -log_acc(-lu);
    g_gumbel[n] = g;
}

// ---------------- propagation (R9 structure; emb0 stores only embA/numA) ----------------
__global__ void emb0_kernel(const float* __restrict__ X) {
    int w = (blockIdx.x * blockDim.x + threadIdx.x) >> 5;
    int lane = threadIdx.x & 31;
    if (w >= Nn) return;
    int s = g_rowptr[w], t = g_rowptr[w + 1];
    float acc = 0.f;
    int p = s;
    if ((p & 1) && p < t) {
        float2 a = g_cv0[p];
        acc = __fadd_rn(acc, __fmul_rn(a.y, X[__float_as_int(a.x) * Dd + lane]));
        p++;
    }
    for (; p + 8 <= t; p += 8) {
        float4 q0 = *(const float4*)&g_cv0[p];
        float4 q1 = *(const float4*)&g_cv0[p + 2];
        float4 q2 = *(const float4*)&g_cv0[p + 4];
        float4 q3 = *(const float4*)&g_cv0[p + 6];
        float x0 = X[__float_as_int(q0.x) * Dd + lane];
        float x1 = X[__float_as_int(q0.z) * Dd + lane];
        float x2 = X[__float_as_int(q1.x) * Dd + lane];
        float x3 = X[__float_as_int(q1.z) * Dd + lane];
        float x4 = X[__float_as_int(q2.x) * Dd + lane];
        float x5 = X[__float_as_int(q2.z) * Dd + lane];
        float x6 = X[__float_as_int(q3.x) * Dd + lane];
        float x7 = X[__float_as_int(q3.z) * Dd + lane];
        acc = __fadd_rn(acc, __fmul_rn(q0.y, x0));
        acc = __fadd_rn(acc, __fmul_rn(q0.w, x1));
        acc = __fadd_rn(acc, __fmul_rn(q1.y, x2));
        acc = __fadd_rn(acc, __fmul_rn(q1.w, x3));
        acc = __fadd_rn(acc, __fmul_rn(q2.y, x4));
        acc = __fadd_rn(acc, __fmul_rn(q2.w, x5));
        acc = __fadd_rn(acc, __fmul_rn(q3.y, x6));
        acc = __fadd_rn(acc, __fmul_rn(q3.w, x7));
    }
    for (; p < t; p++) {
        float2 a = g_cv0[p];
        acc = __fadd_rn(acc, __fmul_rn(a.y, X[__float_as_int(a.x) * Dd + lane]));
    }
    float e0 = __fsub_rn(acc, X[w * Dd + lane]);
    g_embA[w * Dd + lane] = e0;
    if (lane == 0) g_numA[w] = g_order0[w];
}

// COMP==1: embS/numS computed by recurrence from registers (no embS read).
template <int SEL, int COMP, int FINAL>
__global__ void iter_kernel(const float* __restrict__ X, float* score_out) {
    const float2* __restrict__ cv = (COMP == 1) ? g_cv1 : ((COMP == 2) ? g_cv2 : g_cv3);
    const float* __restrict__ ord = (COMP == 1) ? g_order0 : ((COMP == 2) ? g_order1 : g_order2);
    const float* __restrict__ cur  = SEL ? g_embB : g_embA;
    float*       __restrict__ nxt  = SEL ? g_embA : g_embB;
    const float* __restrict__ curn = SEL ? g_numB : g_numA;
    float*       __restrict__ nxtn = SEL ? g_numA : g_numB;
    int w = (blockIdx.x * blockDim.x + threadIdx.x) >> 5;
    int lane = threadIdx.x & 31;
    if (w >= Nn) return;
    int s = g_rowptr[w], t = g_rowptr[w + 1];
    float accE = 0.f, accN = 0.f;
    int p = s;
    if ((p & 1) && p < t) {
        float2 a = cv[p];
        int c = __float_as_int(a.x);
        accE = __fadd_rn(accE, __fmul_rn(a.y, cur[c * Dd + lane]));
        accN = __fadd_rn(accN, __fmul_rn(a.y, curn[c]));
        p++;
    }
    for (; p + 8 <= t; p += 8) {
        float4 q0 = *(const float4*)&cv[p];
        float4 q1 = *(const float4*)&cv[p + 2];
        float4 q2 = *(const float4*)&cv[p + 4];
        float4 q3 = *(const float4*)&cv[p + 6];
        int c0 = __float_as_int(q0.x), c1 = __float_as_int(q0.z);
        int c2 = __float_as_int(q1.x), c3 = __float_as_int(q1.z);
        int c4 = __float_as_int(q2.x), c5 = __float_as_int(q2.z);
        int c6 = __float_as_int(q3.x), c7 = __float_as_int(q3.z);
        float x0 = cur[c0 * Dd + lane], x1 = cur[c1 * Dd + lane];
        float x2 = cur[c2 * Dd + lane], x3 = cur[c3 * Dd + lane];
        float x4 = cur[c4 * Dd + lane], x5 = cur[c5 * Dd + lane];
        float x6 = cur[c6 * Dd + lane], x7 = cur[c7 * Dd + lane];
        float n0 = curn[c0], n1 = curn[c1], n2 = curn[c2], n3 = curn[c3];
        float n4 = curn[c4], n5 = curn[c5], n6 = curn[c6], n7 = curn[c7];
        accE = __fadd_rn(accE, __fmul_rn(q0.y, x0));
        accN = __fadd_rn(accN, __fmul_rn(q0.y, n0));
        accE = __fadd_rn(accE, __fmul_rn(q0.w, x1));
        accN = __fadd_rn(accN, __fmul_rn(q0.w, n1));
        accE = __fadd_rn(accE, __fmul_rn(q1.y, x2));
        accN = __fadd_rn(accN, __fmul_rn(q1.y, n2));
        accE = __fadd_rn(accE, __fmul_rn(q1.w, x3));
        accN = __fadd_rn(accN, __fmul_rn(q1.w, n3));
        accE = __fadd_rn(accE, __fmul_rn(q2.y, x4));
        accN = __fadd_rn(accN, __fmul_rn(q2.y, n4));
        accE = __fadd_rn(accE, __fmul_rn(q2.w, x5));
        accN = __fadd_rn(accN, __fmul_rn(q2.w, n5));
        accE = __fadd_rn(accE, __fmul_rn(q3.y, x6));
        accN = __fadd_rn(accN, __fmul_rn(q3.y, n6));
        accE = __fadd_rn(accE, __fmul_rn(q3.w, x7));
        accN = __fadd_rn(accN, __fmul_rn(q3.w, n7));
    }
    for (; p < t; p++) {
        float2 a = cv[p];
        int c = __float_as_int(a.x);
        accE = __fadd_rn(accE, __fmul_rn(a.y, cur[c * Dd + lane]));
        accN = __fadd_rn(accN, __fmul_rn(a.y, curn[c]));
    }
    float o = ord[w];
    float ce = cur[w * Dd + lane];
    float outE = __fsub_rn(__fsub_rn(accE, ce), __fmul_rn(o, ce));
    float cn = curn[w];
    float outN = __fsub_rn(__fsub_rn(accN, cn), o);

    if (FINAL == 0) {
        nxt[w * Dd + lane] = outE;
        if (COMP == 1) {
            // embS = e0 + e1 ; numS = n0 + n1 (recurrence; ce/cn are e0/n0)
            g_embS[w * Dd + lane] = __fadd_rn(ce, outE);
            if (lane == 0) {
                nxtn[w] = outN;
                g_numS[w] = __fadd_rn(cn, outN);
            }
        } else {
            g_embS[w * Dd + lane] = __fadd_rn(g_embS[w * Dd + lane], outE);
            if (lane == 0) {
                nxtn[w] = outN;
                g_numS[w] = __fadd_rn(g_numS[w], outN);
            }
        }
    } else {
        float embS = __fadd_rn(g_embS[w * Dd + lane], outE);
        float numS = __fadd_rn(g_numS[w], outN);
        float den = __fadd_rn(numS, 1e-8f);
        float sv = __fdiv_rn(embS, den);
        float ev = X[w * Dd + lane];

        float p1 = __fmul_rn(sv, sv);
        float sq = 0.f;
#pragma unroll
        for (int d = 0; d < 32; d++) sq = __fadd_rn(sq, __shfl_sync(0xffffffffu, p1, d));
        float nr = fmaxf(__fsqrt_rn(sq), 1e-12f);

        float p2 = __fmul_rn(ev, ev);
        float sq2 = 0.f;
#pragma unroll
        for (int d = 0; d < 32; d++) sq2 = __fadd_rn(sq2, __shfl_sync(0xffffffffu, p2, d));
        float nr2 = fmaxf(__fsqrt_rn(sq2), 1e-12f);

        float prod = __fmul_rn(__fdiv_rn(sv, nr), __fdiv_rn(ev, nr2));
        float dot = 0.f;
#pragma unroll
        for (int d = 0; d < 32; d++) dot = __fadd_rn(dot, __shfl_sync(0xffffffffu, prod, d));

        if (lane == 0) {
            float score = __fadd_rn(dot, g_gumbel[w]);
            if (score_out) score_out[w] = score;
            unsigned ub = __float_as_uint(score);
            g_keys[w] = (ub & 0x80000000u) ? ~ub : (ub | 0x80000000u);
        }
    }
}

// ---------------- top-k (R9: radix select -> compact -> bitonic) ----------------
__global__ void select_kernel() {
    __shared__ int hist[256];
    __shared__ unsigned s_prefix, s_mask;
    __shared__ int s_k;
    int tid = threadIdx.x;
    if (tid == 0) { s_prefix = 0u; s_mask = 0u; s_k = Kk; }
    __syncthreads();
    for (int shift = 24; shift >= 0; shift -= 8) {
        if (tid < 256) hist[tid] = 0;
        __syncthreads();
        unsigned mask = s_mask, pref = s_prefix;
        for (int i = tid; i < Nn; i += 1024) {
            unsigned key = g_keys[i];
            if ((key & mask) == pref) atomicAdd(&hist[(key >> shift) & 255u], 1);
        }
        __syncthreads();
        if (tid == 0) {
            int k = s_k;
            int v = 255;
            for (; v > 0; v--) { int c = hist[v]; if (k <= c) break; k -= c; }
            s_prefix = pref | ((unsigned)v << shift);
            s_mask = mask | (0xFFu << shift);
            s_k = k;
        }
        __syncthreads();
    }
    if (tid == 0) {
        g_kth = s_prefix;
        g_cntG = 0; g_cntE = 0;
    }
}

__global__ void compact_kernel() {
    int i = blockIdx.x * blockDim.x + threadIdx.x;
    if (i >= Nn) return;
    unsigned key = g_keys[i];
    unsigned T = g_kth;
    if (key > T) {
        int p = atomicAdd(&g_cntG, 1);
        if (p < 2048) g_candG[p] = (((unsigned long long)(~key)) << 32) | (unsigned)i;
    } else if (key == T) {
        int p = atomicAdd(&g_cntE, 1);
        if (p < 2048) g_candE[p] = i;
    }
    g_counts[i] = 0;
    if (i < 8) g_bar[i] = 0u;
}

__global__ void finalsort_kernel(float* cand_out) {
    __shared__ unsigned long long sg[1024];
    __shared__ int se[2048];
    int tid = threadIdx.x;
    int cntG = g_cntG; if (cntG > 1024) cntG = 1024;
    int cntE = g_cntE; if (cntE > 2048) cntE = 2048;
    sg[tid] = (tid < cntG) ? g_candG[tid] : 0xFFFFFFFFFFFFFFFFull;
    se[tid]        = (tid < cntE)        ? g_candE[tid]        : 0x7FFFFFFF;
    se[tid + 1024] = (tid + 1024 < cntE) ? g_candE[tid + 1024] : 0x7FFFFFFF;
    __syncthreads();
    for (int k = 2; k <= 1024; k <<= 1)
        for (int j = k >> 1; j > 0; j >>= 1) {
            int ixj = tid ^ j;
            if (ixj > tid) {
                bool up = ((tid & k) == 0);
                unsigned long long a = sg[tid], b = sg[ixj];
                if ((a > b) == up) { sg[tid] = b; sg[ixj] = a; }
            }
            __syncthreads();
        }
    for (int k = 2; k <= 2048; k <<= 1)
        for (int j = k >> 1; j > 0; j >>= 1) {
            for (int t = tid; t < 2048; t += 1024) {
                int ixj = t ^ j;
                if (ixj > t) {
                    bool up = ((t & k) == 0);
                    int a = se[t], b = se[ixj];
                    if ((a > b) == up) { se[t] = b; se[ixj] = a; }
                }
            }
            __syncthreads();
        }
    if (tid < Kk && cand_out) {
        int idx = (tid < cntG) ? (int)(sg[tid] & 0xFFFFFFFFull) : se[tid - cntG];
        cand_out[tid] = (float)idx;
    }
}

// ---------------- launch ----------------
extern "C" void kernel_launch(void* const* d_in, const int* in_sizes, int n_in,
                              void* d_out, int out_size) {
    const int*   edge_index = (const int*)d_in[0];
    const float* adj_values = (const float*)d_in[1];
    const float* embeds     = (const float*)d_in[2];
    const int* rows = edge_index;
    const int* cols = edge_index + Ee;
    float* out = (float*)d_out;

    float* score_out = nullptr;
    float* cand_out  = nullptr;
    if (out_size >= Nn + Kk)      { score_out = out; cand_out = out + Nn; }
    else if (out_size == Nn)      { score_out = out; }
    else if (out_size == Kk)      { cand_out = out; }
    else                          { score_out = out; }

    unsigned fk[3][2];
    for (int i = 0; i < 3; i++) tf2x32(0u, 42u, 0u, (unsigned)i, fk[i][0], fk[i][1]);

    const int TB = 256;
    int warpBlocks = (Nn * 32 + TB - 1) / TB;
    build_kernel<<<GB, GBT>>>(rows, cols, adj_values,               // 1
                              fk[0][0], fk[0][1],
                              fk[1][0], fk[1][1],
                              fk[2][0], fk[2][1]);
    gumbel_kernel<<<(Nn + TB - 1) / TB, TB>>>();                    // 2
    emb0_kernel<<<warpBlocks, TB>>>(embeds);                        // 3
    iter_kernel<0, 1, 0><<<warpBlocks, TB>>>(nullptr, nullptr);     // 4 <- ncu window
    iter_kernel<1, 2, 0><<<warpBlocks, TB>>>(nullptr, nullptr);     // 5
    iter_kernel<0, 3, 1><<<warpBlocks, TB>>>(embeds, score_out);    // 6 (fused score)
    select_kernel<<<1, 1024>>>();                                   // 7
    compact_kernel<<<(Nn + TB - 1) / TB, TB>>>();                   // 8 (+cleanup)
    finalsort_kernel<<<1, 1024>>>(cand_out);                        // 9
}